// round 5
// baseline (speedup 1.0000x reference)
#include <cuda_runtime.h>
#include <cuda_fp16.h>

#define D  64
#define NA 64
#define MAX_ITEM 100000
#define MAX_BZ   1024

// Scratch tables (allocation-free: __device__ globals)
__device__ __align__(16) float  g_P[MAX_BZ * NA];              // 256 KB fp32
__device__ __align__(16) __half g_Qh[(size_t)MAX_ITEM * NA];   // 12.8 MB fp16, L2-resident

// ---- packed f32x2 FMA (Blackwell): d = a*b + d, lanewise on 2 floats ----
__device__ __forceinline__ void ffma2(unsigned long long& acc,
                                      unsigned long long a,
                                      unsigned long long b) {
    asm("fma.rn.f32x2 %0, %1, %2, %0;" : "+l"(acc) : "l"(a), "l"(b));
}
union F2U { float2 f; unsigned long long u; };
union F4U { float4 f; struct { unsigned long long lo, hi; } u; };

// ---------------------------------------------------------------------------
// Fused prep: blocks [0, QB) compute fp16 Qd table (+bias folded);
// blocks [QB, QB+PB) compute P.
// A staged as A2[d][33] float2: A2[d][l] = (A[2l][d], A[2l+1][d]).
//   read in dot loop: LDS.64, conflict-free per 16-lane phase.
// Item tile staged DUPLICATED: per d, two float4 = (i0,i0,i1,i1),(i2,i2,i3,i3)
//   so each FFMA2 broadcast operand is a ready register pair (no pack MOVs).
// ---------------------------------------------------------------------------
__global__ void __launch_bounds__(256) prep_kernel(
        const int* __restrict__ uidx,
        const float* __restrict__ Uemb,
        const float* __restrict__ Iemb,
        const float* __restrict__ A,
        const float* __restrict__ Rel,
        const float* __restrict__ bias,
        int bz, int nitem, int QB) {
    __shared__ __align__(16) float2 A2[64][33];        // 16.9 KB
    __shared__ __align__(16) float  sR[128];           // qd: RpA|RnA ; p: RuA
    __shared__ __align__(16) float2 ismd[8][288];      // dup item tile / warp (18 KB)

    int t = threadIdx.x;
    // fill A2: element a of A row-major -> A2[d][a>>1] component (a&1)
    for (int idx = t; idx < 64 * 64; idx += 256) {
        int a = idx >> 6, d = idx & 63;
        ((float*)&A2[d][a >> 1])[a & 1] = A[idx];      // coalesced global read
    }
    __syncthreads();

    int w = t >> 5, lane = t & 31;
    bool isQ = blockIdx.x < QB;

    // ---- per-block relation projections (A from smem, Rel broadcast) ----
    if (isQ) {
        if (t < 128) {
            int rr = 1 + (t >> 6);       // 1 = Rip, 2 = Rin
            int a  = t & 63;
            const float* rv = Rel + rr * D;
            float s = 0.f;
#pragma unroll
            for (int d = 0; d < 64; d++)
                s += rv[d] * ((const float*)&A2[d][a >> 1])[a & 1];
            sR[t] = s;                    // [0,64)=RpA, [64,128)=RnA
        }
    } else {
        if (t < 64) {
            int a = t;
            float s = 0.f;
#pragma unroll
            for (int d = 0; d < 64; d++)
                s += Rel[d] * ((const float*)&A2[d][a >> 1])[a & 1];
            sR[t] = s;                    // RuA
        }
    }
    __syncthreads();

    if (isQ) {
        // ================= Qd blocks: 64 items/block =================
        float2 rp = ((const float2*)sR)[lane];          // aspects (2l, 2l+1)
        float2 rn = ((const float2*)(sR + 64))[lane];
        float2* wdup = ismd[w];
        int blockBase = blockIdx.x * 64;
#pragma unroll 1
        for (int it = 0; it < 2; it++) {
            int base4 = blockBase + w * 8 + it * 4;     // 4 consecutive items
            if (base4 >= nitem) break;                  // nitem % 4 == 0

            // Cooperative load: 4 rows = 256 contiguous floats.
            const float4* g4 = (const float4*)(Iemb + (size_t)base4 * D);
            float4 v1 = g4[lane];
            float4 v2 = g4[lane + 32];
            __syncwarp();
            {
                // float4 #f: item j=f>>4, covers d=4q..4q+3 (q=f&15).
                // dup slot for (d=4q+k, item j): float2 index 18q + 4k + j
                int f, j, q;
                f = lane;      j = f >> 4; q = f & 15;
#pragma unroll
                for (int k = 0; k < 4; k++) {
                    float v = ((float*)&v1)[k];
                    wdup[18 * q + 4 * k + j] = make_float2(v, v);
                }
                f = lane + 32; j = f >> 4; q = f & 15;
#pragma unroll
                for (int k = 0; k < 4; k++) {
                    float v = ((float*)&v2)[k];
                    wdup[18 * q + 4 * k + j] = make_float2(v, v);
                }
            }
            __syncwarp();

            unsigned long long acc0 = 0ull, acc1 = 0ull, acc2 = 0ull, acc3 = 0ull;
#pragma unroll
            for (int d = 0; d < 64; d++) {
                F2U a2; a2.f = A2[d][lane];                          // LDS.64 cf
                int f4base = 9 * (d >> 2) + 2 * (d & 3);
                F4U d0; d0.f = ((const float4*)wdup)[f4base];        // (i0,i0,i1,i1)
                F4U d1; d1.f = ((const float4*)wdup)[f4base + 1];    // (i2,i2,i3,i3)
                ffma2(acc0, a2.u, d0.u.lo);
                ffma2(acc1, a2.u, d0.u.hi);
                ffma2(acc2, a2.u, d1.u.lo);
                ffma2(acc3, a2.u, d1.u.hi);
            }

            unsigned long long accs[4] = {acc0, acc1, acc2, acc3};
#pragma unroll
            for (int j = 0; j < 4; j++) {
                F2U L; L.u = accs[j];
                // shift-free softmax: |logit| <~ 50 << 88 (fp32 exp overflow)
                float ep0 = __expf(L.f.x + rp.x), ep1 = __expf(L.f.y + rp.y);
                float en0 = __expf(L.f.x + rn.x), en1 = __expf(L.f.y + rn.y);
                float sp = ep0 + ep1, sn = en0 + en1;
#pragma unroll
                for (int o = 16; o; o >>= 1) {
                    sp += __shfl_xor_sync(0xffffffffu, sp, o);
                    sn += __shfl_xor_sync(0xffffffffu, sn, o);
                }
                float ipv = __fdividef(1.f, sp);
                float inv = __fdividef(1.f, sn);
                float bb  = bias[base4 + j];            // warp-uniform broadcast
                float q0 = ep0 * ipv - en0 * inv + bb;
                float q1 = ep1 * ipv - en1 * inv + bb;
                __half2* orow = (__half2*)(g_Qh + (size_t)(base4 + j) * NA);
                orow[lane] = __floats2half2_rn(q0, q1); // 128B coalesced row
            }
        }
    } else {
        // ================= P blocks: 8 users/block =================
        float2 ru = ((const float2*)sR)[lane];
        int row = (blockIdx.x - QB) * 8 + w;
        if (row >= bz) return;
        const float* U = Uemb + (size_t)uidx[row] * D;
        float* us = (float*)ismd[w];
        ((float2*)us)[lane] = ((const float2*)U)[lane];
        __syncwarp();

        float acc0 = 0.f, acc1 = 0.f;
#pragma unroll
        for (int d = 0; d < 64; d++) {
            float  u  = us[d];
            float2 a2 = A2[d][lane];
            acc0 += u * a2.x;
            acc1 += u * a2.y;
        }
        float l0 = acc0 + ru.x, l1 = acc1 + ru.y;
        float m = fmaxf(l0, l1);
#pragma unroll
        for (int o = 16; o; o >>= 1) m = fmaxf(m, __shfl_xor_sync(0xffffffffu, m, o));
        float e0 = __expf(l0 - m), e1 = __expf(l1 - m);
        float s = e0 + e1;
#pragma unroll
        for (int o = 16; o; o >>= 1) s += __shfl_xor_sync(0xffffffffu, s, o);
        float inv = __fdividef(1.f, s);
        ((float2*)(g_P + row * NA))[lane] = make_float2(e0 * inv, e1 * inv);
    }
}

// ---------------------------------------------------------------------------
// Main: ratings[b,n] = P[b] . Qh[item[b,n]]  (bias pre-folded); softmax over n.
// One block per b. 8-lane groups gather one fp16 row = ONE 128B line (LDG.128).
// Batched x4: all loads issued before any consume.
// ---------------------------------------------------------------------------
__global__ void __launch_bounds__(256) main_kernel(
        const int* __restrict__ iidx,
        float* __restrict__ out, int ns) {
    __shared__ __align__(16) float Ps[64];
    __shared__ __align__(16) float rat[1024];
    __shared__ float red[8];
    int b = blockIdx.x;
    int t = threadIdx.x;
    if (t < 16) ((float4*)Ps)[t] = ((const float4*)(g_P + b * 64))[t];
    __syncthreads();

    int w = t >> 5, lane = t & 31, g = lane >> 3, q = lane & 7;
    float4 pA = ((float4*)Ps)[2 * q];       // aspects 8q..8q+3
    float4 pB = ((float4*)Ps)[2 * q + 1];   // aspects 8q+4..8q+7
    const int* idxrow = iidx + (size_t)b * ns;
    int nsp = (ns + 127) & ~127;   // padded bound (128 samples/iter)

    for (int s0 = w * 16; s0 < nsp; s0 += 128) {
        uint4 raw[4];
        // -------- batched load phase: no consume until all issued --------
#pragma unroll
        for (int k = 0; k < 4; k++) {
            int s = s0 + k * 4 + g;
            int item = (s < ns) ? idxrow[s] : 0;
            raw[k] = ((const uint4*)(g_Qh + (size_t)item * NA))[q]; // halves 8q..8q+7
        }
        // -------- compute + reduce phase --------
#pragma unroll
        for (int k = 0; k < 4; k++) {
            float2 f0 = __half22float2(*(__half2*)&raw[k].x);
            float2 f1 = __half22float2(*(__half2*)&raw[k].y);
            float2 f2 = __half22float2(*(__half2*)&raw[k].z);
            float2 f3 = __half22float2(*(__half2*)&raw[k].w);
            float r = f0.x * pA.x + f0.y * pA.y + f1.x * pA.z + f1.y * pA.w
                    + f2.x * pB.x + f2.y * pB.y + f3.x * pB.z + f3.y * pB.w;
            r += __shfl_xor_sync(0xffffffffu, r, 1);
            r += __shfl_xor_sync(0xffffffffu, r, 2);
            r += __shfl_xor_sync(0xffffffffu, r, 4);
            int s = s0 + k * 4 + g;
            if (s < ns && q == 0) rat[s] = r;
        }
    }
    __syncthreads();

    // block softmax over rat[0..ns)
    float m = -1e30f;
    for (int s = t; s < ns; s += 256) m = fmaxf(m, rat[s]);
#pragma unroll
    for (int o = 16; o; o >>= 1) m = fmaxf(m, __shfl_xor_sync(0xffffffffu, m, o));
    if (lane == 0) red[w] = m;
    __syncthreads();
    if (t == 0) {
        float v = red[0];
#pragma unroll
        for (int i = 1; i < 8; i++) v = fmaxf(v, red[i]);
        red[0] = v;
    }
    __syncthreads();
    m = red[0];
    __syncthreads();   // protect red[] before sum phase reuses it

    float sum = 0.f;
    for (int s = t; s < ns; s += 256) {
        float e = __expf(rat[s] - m);
        rat[s] = e;
        sum += e;
    }
#pragma unroll
    for (int o = 16; o; o >>= 1) sum += __shfl_xor_sync(0xffffffffu, sum, o);
    if (lane == 0) red[w] = sum;
    __syncthreads();
    if (t == 0) {
        float v = red[0];
#pragma unroll
        for (int i = 1; i < 8; i++) v += red[i];
        red[0] = v;
    }
    __syncthreads();
    float inv = __fdividef(1.f, red[0]);
    float* orow = out + (size_t)b * ns;
    for (int s = t; s < ns; s += 256) orow[s] = rat[s] * inv;
}

// ---------------------------------------------------------------------------
// Launch
// ---------------------------------------------------------------------------
extern "C" void kernel_launch(void* const* d_in, const int* in_sizes, int n_in,
                              void* d_out, int out_size) {
    const int*   uidx = (const int*)d_in[0];
    const int*   iidx = (const int*)d_in[1];
    const float* Uemb = (const float*)d_in[2];
    const float* Iemb = (const float*)d_in[3];
    const float* A    = (const float*)d_in[4];
    const float* Rel  = (const float*)d_in[5];
    const float* bias = (const float*)d_in[6];
    float* out = (float*)d_out;

    int bz    = in_sizes[0];
    int ns    = in_sizes[1] / bz;
    int nitem = in_sizes[3] / D;

    int QB = (nitem + 63) / 64;
    int PB = (bz + 7) / 8;

    prep_kernel<<<QB + PB, 256>>>(uidx, Uemb, Iemb, A, Rel, bias, bz, nitem, QB);
    main_kernel<<<bz, 256>>>(iidx, out, ns);
}

// round 6
// speedup vs baseline: 1.3573x; 1.3573x over previous
#include <cuda_runtime.h>
#include <cuda_fp16.h>

#define D  64
#define NA 64
#define MAX_ITEM 100000
#define MAX_BZ   1024

// Scratch tables (allocation-free: __device__ globals)
__device__ __align__(16) __half g_Ph[MAX_BZ * NA];             // 128 KB fp16 P
__device__ __align__(16) __half g_Qh[(size_t)MAX_ITEM * NA];   // 12.8 MB fp16 Qd+bias

// ---------------------------------------------------------------------------
// Fused prep: blocks [0, QB) compute fp16 Qd table (+bias folded);
// blocks [QB, QB+PB) compute fp16 P.
// A staged as A2[d][33] float2: A2[d][l] = (A[2l][d], A[2l+1][d]).
//   dot-loop read A2[d][lane]: LDS.64, banks (2d+2l, +1) distinct per 16-lane
//   phase -> conflict-free. Lane owns aspect pair (2l, 2l+1) -> direct half2 out.
// Item tiles T[w][0/1]: per d one float4 = items 0-3 / 4-7 (LDS.128 broadcast).
// Per d: 1 LDS.64 + 2 LDS.128 + 16 FFMA  = 8 items (3 smem wavefronts).
// ---------------------------------------------------------------------------
__global__ void __launch_bounds__(256) prep_kernel(
        const int* __restrict__ uidx,
        const float* __restrict__ Uemb,
        const float* __restrict__ Iemb,
        const float* __restrict__ A,
        const float* __restrict__ Rel,
        const float* __restrict__ bias,
        int bz, int nitem, int QB) {
    __shared__ __align__(16) float2 A2[64][33];       // 16.9 KB
    __shared__ __align__(16) float  sR[128];          // qd: RpA|RnA ; p: RuA
    __shared__ __align__(16) float4 T[8][2][80];      // 20.5 KB: 2 item tiles/warp

    int t = threadIdx.x;
    // fill A2: A row-major element (a, d) -> A2[d][a>>1] component (a&1)
    for (int idx = t; idx < 64 * 64; idx += 256) {
        int a = idx >> 6, d = idx & 63;
        ((float*)&A2[d][a >> 1])[a & 1] = A[idx];     // coalesced global read
    }
    __syncthreads();

    int w = t >> 5, lane = t & 31;
    bool isQ = blockIdx.x < QB;

    // ---- per-block relation projections (A from smem, Rel broadcast) ----
    if (isQ) {
        if (t < 128) {
            int rr = 1 + (t >> 6);       // 1 = Rip, 2 = Rin
            int a  = t & 63;
            const float* rv = Rel + rr * D;
            float s = 0.f;
#pragma unroll
            for (int d = 0; d < 64; d++)
                s += rv[d] * ((const float*)&A2[d][a >> 1])[a & 1];
            sR[t] = s;                    // [0,64)=RpA, [64,128)=RnA
        }
    } else {
        if (t < 64) {
            int a = t;
            float s = 0.f;
#pragma unroll
            for (int d = 0; d < 64; d++)
                s += Rel[d] * ((const float*)&A2[d][a >> 1])[a & 1];
            sR[t] = s;                    // RuA
        }
    }
    __syncthreads();

    if (isQ) {
        // ======== Qd blocks: 8 warps x 8 items = 64 items/block ========
        float2 rp = ((const float2*)sR)[lane];          // aspects (2l, 2l+1)
        float2 rn = ((const float2*)(sR + 64))[lane];
        int base8 = blockIdx.x * 64 + w * 8;            // 8 consecutive items
        if (base8 < nitem) {                            // nitem % 8 == 0
            // Cooperative load: 8 rows = 512 contiguous floats = 128 float4.
            const float4* g4 = (const float4*)(Iemb + (size_t)base8 * D);
            float4 v[4];
#pragma unroll
            for (int u = 0; u < 4; u++) v[u] = g4[lane + u * 32];
            // scatter: float4 #f -> item j=f>>4 (0..7), q=f&15 covers d=4q..4q+3
            // tile (j>>2), slot 5q+k, component j&3
#pragma unroll
            for (int u = 0; u < 4; u++) {
                int f = lane + u * 32, j = f >> 4, q = f & 15;
                float* dst = (float*)&T[w][j >> 2][0];
#pragma unroll
                for (int k = 0; k < 4; k++)
                    dst[(5 * q + k) * 4 + (j & 3)] = ((float*)&v[u])[k];
            }
            __syncwarp();

            float2 acc[8];
#pragma unroll
            for (int j = 0; j < 8; j++) acc[j] = make_float2(0.f, 0.f);
#pragma unroll
            for (int d = 0; d < 64; d++) {
                float2 a2 = A2[d][lane];              // LDS.64 conflict-free
                int slot = d + (d >> 2);              // 5*(d>>2) + (d&3)
                float4 i0 = T[w][0][slot];            // items 0-3, LDS.128 bcast
                float4 i1 = T[w][1][slot];            // items 4-7, LDS.128 bcast
                acc[0].x += i0.x * a2.x; acc[0].y += i0.x * a2.y;
                acc[1].x += i0.y * a2.x; acc[1].y += i0.y * a2.y;
                acc[2].x += i0.z * a2.x; acc[2].y += i0.z * a2.y;
                acc[3].x += i0.w * a2.x; acc[3].y += i0.w * a2.y;
                acc[4].x += i1.x * a2.x; acc[4].y += i1.x * a2.y;
                acc[5].x += i1.y * a2.x; acc[5].y += i1.y * a2.y;
                acc[6].x += i1.z * a2.x; acc[6].y += i1.z * a2.y;
                acc[7].x += i1.w * a2.x; acc[7].y += i1.w * a2.y;
            }

#pragma unroll
            for (int j = 0; j < 8; j++) {
                // shift-free softmax: |logit| <~ 50 << 88 (fp32 exp overflow)
                float ep0 = __expf(acc[j].x + rp.x), ep1 = __expf(acc[j].y + rp.y);
                float en0 = __expf(acc[j].x + rn.x), en1 = __expf(acc[j].y + rn.y);
                float sp = ep0 + ep1, sn = en0 + en1;
#pragma unroll
                for (int o = 16; o; o >>= 1) {
                    sp += __shfl_xor_sync(0xffffffffu, sp, o);
                    sn += __shfl_xor_sync(0xffffffffu, sn, o);
                }
                float ipv = __fdividef(1.f, sp);
                float inv = __fdividef(1.f, sn);
                float bb  = bias[base8 + j];          // warp-uniform broadcast
                float q0 = ep0 * ipv - en0 * inv + bb;
                float q1 = ep1 * ipv - en1 * inv + bb;
                __half2* orow = (__half2*)(g_Qh + (size_t)(base8 + j) * NA);
                orow[lane] = __floats2half2_rn(q0, q1);  // 128B coalesced row
            }
        }
    } else {
        // ================= P blocks: 8 users/block =================
        float2 ru = ((const float2*)sR)[lane];
        int row = (blockIdx.x - QB) * 8 + w;
        if (row >= bz) return;
        const float* U = Uemb + (size_t)uidx[row] * D;
        float* us = (float*)&T[w][0][0];
        ((float2*)us)[lane] = ((const float2*)U)[lane];
        __syncwarp();

        float acc0 = 0.f, acc1 = 0.f;
#pragma unroll
        for (int d = 0; d < 64; d++) {
            float  u  = us[d];
            float2 a2 = A2[d][lane];
            acc0 += u * a2.x;
            acc1 += u * a2.y;
        }
        float l0 = acc0 + ru.x, l1 = acc1 + ru.y;
        float m = fmaxf(l0, l1);
#pragma unroll
        for (int o = 16; o; o >>= 1) m = fmaxf(m, __shfl_xor_sync(0xffffffffu, m, o));
        float e0 = __expf(l0 - m), e1 = __expf(l1 - m);
        float s = e0 + e1;
#pragma unroll
        for (int o = 16; o; o >>= 1) s += __shfl_xor_sync(0xffffffffu, s, o);
        float inv = __fdividef(1.f, s);
        ((__half2*)(g_Ph + row * NA))[lane] =
            __floats2half2_rn(e0 * inv, e1 * inv);
    }
}

// ---------------------------------------------------------------------------
// Main: ratings[b,n] = P[b] . Qh[item[b,n]]  (bias pre-folded); softmax over n.
// One block per b. 8-lane groups gather one fp16 row = ONE 128B line.
// All-fp16 dot: 4 HFMA2 per sample-chunk, zero converts in the hot loop.
// Batched x8: 8 LDG.128 in flight before any consume.
// ---------------------------------------------------------------------------
__global__ void __launch_bounds__(256) main_kernel(
        const int* __restrict__ iidx,
        float* __restrict__ out, int ns) {
    __shared__ __align__(16) uint4 Psh[8];
    __shared__ __align__(16) float rat[1024];
    __shared__ float red[8];
    int b = blockIdx.x;
    int t = threadIdx.x;
    if (t < 8) Psh[t] = ((const uint4*)(g_Ph + b * 64))[t];
    __syncthreads();

    int w = t >> 5, lane = t & 31, g = lane >> 3, q = lane & 7;
    uint4 praw = Psh[q];                 // P halves 8q..8q+7 (pairs 2l,2l+1)
    __half2 p0 = *(__half2*)&praw.x, p1 = *(__half2*)&praw.y;
    __half2 p2 = *(__half2*)&praw.z, p3 = *(__half2*)&praw.w;
    const int* idxrow = iidx + (size_t)b * ns;
    int nsp = (ns + 255) & ~255;         // padded bound (256 samples/iter)

    for (int s0 = w * 32; s0 < nsp; s0 += 256) {
        uint4 raw[8];
        // -------- batched load phase: no consume until all issued --------
#pragma unroll
        for (int k = 0; k < 8; k++) {
            int s = s0 + k * 4 + g;
            int item = (s < ns) ? idxrow[s] : 0;
            raw[k] = ((const uint4*)(g_Qh + (size_t)item * NA))[q];
        }
        // -------- compute + reduce phase (all-fp16 dot) --------
#pragma unroll
        for (int k = 0; k < 8; k++) {
            __half2 acc = __hmul2(*(__half2*)&raw[k].x, p0);
            acc = __hfma2(*(__half2*)&raw[k].y, p1, acc);
            acc = __hfma2(*(__half2*)&raw[k].z, p2, acc);
            acc = __hfma2(*(__half2*)&raw[k].w, p3, acc);
            float2 f = __half22float2(acc);
            float r = f.x + f.y;
            r += __shfl_xor_sync(0xffffffffu, r, 1);
            r += __shfl_xor_sync(0xffffffffu, r, 2);
            r += __shfl_xor_sync(0xffffffffu, r, 4);
            int s = s0 + k * 4 + g;
            if (s < ns && q == 0) rat[s] = r;
        }
    }
    __syncthreads();

    // block softmax over rat[0..ns)
    float m = -1e30f;
    for (int s = t; s < ns; s += 256) m = fmaxf(m, rat[s]);
#pragma unroll
    for (int o = 16; o; o >>= 1) m = fmaxf(m, __shfl_xor_sync(0xffffffffu, m, o));
    if (lane == 0) red[w] = m;
    __syncthreads();
    if (t == 0) {
        float v = red[0];
#pragma unroll
        for (int i = 1; i < 8; i++) v = fmaxf(v, red[i]);
        red[0] = v;
    }
    __syncthreads();
    m = red[0];
    __syncthreads();   // protect red[] before sum phase reuses it

    float sum = 0.f;
    for (int s = t; s < ns; s += 256) {
        float e = __expf(rat[s] - m);
        rat[s] = e;
        sum += e;
    }
#pragma unroll
    for (int o = 16; o; o >>= 1) sum += __shfl_xor_sync(0xffffffffu, sum, o);
    if (lane == 0) red[w] = sum;
    __syncthreads();
    if (t == 0) {
        float v = red[0];
#pragma unroll
        for (int i = 1; i < 8; i++) v += red[i];
        red[0] = v;
    }
    __syncthreads();
    float inv = __fdividef(1.f, red[0]);
    float* orow = out + (size_t)b * ns;
    for (int s = t; s < ns; s += 256) orow[s] = rat[s] * inv;
}

// ---------------------------------------------------------------------------
// Launch
// ---------------------------------------------------------------------------
extern "C" void kernel_launch(void* const* d_in, const int* in_sizes, int n_in,
                              void* d_out, int out_size) {
    const int*   uidx = (const int*)d_in[0];
    const int*   iidx = (const int*)d_in[1];
    const float* Uemb = (const float*)d_in[2];
    const float* Iemb = (const float*)d_in[3];
    const float* A    = (const float*)d_in[4];
    const float* Rel  = (const float*)d_in[5];
    const float* bias = (const float*)d_in[6];
    float* out = (float*)d_out;

    int bz    = in_sizes[0];
    int ns    = in_sizes[1] / bz;
    int nitem = in_sizes[3] / D;

    int QB = (nitem + 63) / 64;
    int PB = (bz + 7) / 8;

    prep_kernel<<<QB + PB, 256>>>(uidx, Uemb, Iemb, A, Rel, bias, bz, nitem, QB);
    main_kernel<<<bz, 256>>>(iidx, out, ns);
}